// round 1
// baseline (speedup 1.0000x reference)
#include <cuda_runtime.h>

// ---------------------------------------------------------------------------
// Net_22625887715641 on GB300 (sm_103a)
//
// Pipeline:
//   K1 feat_kernel : 11x11(x3) valid convs -> g_feat[2][32][384][384] (raw)
//   K2 norm_kernel : channel-sum normalize; input0 -> d_out (x1),
//                    input1 -> in-place g_feat[1] (x1_prev)
//   K3 corr_kernel : x2[o,d,h,w] = (1/362^2) * sum_{p,q} x1c[o,p,q]*x1p[d,p+h,q+w]
//                    register-sliding-window fp32, FMA-bound
//
// Output layout in d_out (float):
//   [0 .. 4718592)            x1  as [32][384][384]
//   [4718592 .. 5260288)      x2  as [32(o)][32(d)][23][23]
// ---------------------------------------------------------------------------

#define X1_ELEMS   (32 * 384 * 384)          // 4718592
#define FEAT_ELEMS (2 * X1_ELEMS)

__device__ float   g_feat[FEAT_ELEMS];       // raw feats, then normalized (v=1 in place)
__constant__ float c_ft[16 * 3 * 11 * 11];   // 5808
__constant__ float c_fn[16 * 11 * 11];       // 1936

// ===========================================================================
// Kernel 1: features.
// Block: (blockIdx.z = v, blockIdx.y = y-tile of 8 rows, blockIdx.x = x-tile of 64)
// 256 threads, 8 task-iterations: task = (c[32], yy[8], xc[8]); each thread
// computes 8 consecutive x pixels for one (c, yy).
// ===========================================================================
__global__ void __launch_bounds__(256) feat_kernel(const float* __restrict__ x0,
                                                   const float* __restrict__ x1in)
{
    __shared__ __align__(16) float s_in[3 * 18 * 76];  // rows padded 74->76 for float4

    const int v   = blockIdx.z;
    const float* src = v ? x1in : x0;
    const int y0  = blockIdx.y * 8;
    const int xb  = blockIdx.x * 64;

    // Load input tile: t in [0,3), rows y0..y0+17, cols xb..xb+73 (always in-bounds)
    for (int e = threadIdx.x; e < 3 * 18 * 74; e += 256) {
        int t   = e / (18 * 74);
        int rem = e % (18 * 74);
        int r   = rem / 74;
        int cc  = rem % 74;
        s_in[(t * 18 + r) * 76 + cc] = src[(t * 394 + (y0 + r)) * 394 + xb + cc];
    }
    __syncthreads();

    for (int it = 0; it < 8; it++) {
        int task = it * 256 + threadIdx.x;   // 0..2047
        int c    = task >> 6;                // 0..31 (warp-uniform)
        int rem  = task & 63;
        int yy   = rem >> 3;                 // 0..7
        int xc   = rem & 7;                  // 0..7

        float acc[8];
#pragma unroll
        for (int k = 0; k < 8; k++) acc[k] = 0.f;

        if (c < 16) {
            const float* fb = c_ft + c * 363;
            for (int t = 0; t < 3; t++) {
                for (int i = 0; i < 11; i++) {
                    const float4* rowp = reinterpret_cast<const float4*>(
                        &s_in[(t * 18 + (yy + i)) * 76 + xc * 8]);
                    float w[20];
#pragma unroll
                    for (int m = 0; m < 5; m++) {
                        float4 f4 = rowp[m];
                        w[4 * m] = f4.x; w[4 * m + 1] = f4.y;
                        w[4 * m + 2] = f4.z; w[4 * m + 3] = f4.w;
                    }
#pragma unroll
                    for (int j = 0; j < 11; j++) {
                        float f = fb[t * 121 + i * 11 + j];
#pragma unroll
                        for (int k = 0; k < 8; k++) acc[k] += f * w[j + k];
                    }
                }
            }
#pragma unroll
            for (int k = 0; k < 8; k++) acc[k] = fmaxf(acc[k], 0.f) * 0.5f;
        } else {
            const float* fb = c_fn + (c - 16) * 121;
            const int t = 2;  // last frame only
            for (int i = 0; i < 11; i++) {
                const float4* rowp = reinterpret_cast<const float4*>(
                    &s_in[(t * 18 + (yy + i)) * 76 + xc * 8]);
                float w[20];
#pragma unroll
                for (int m = 0; m < 5; m++) {
                    float4 f4 = rowp[m];
                    w[4 * m] = f4.x; w[4 * m + 1] = f4.y;
                    w[4 * m + 2] = f4.z; w[4 * m + 3] = f4.w;
                }
#pragma unroll
                for (int j = 0; j < 11; j++) {
                    float f = fb[i * 11 + j];
#pragma unroll
                    for (int k = 0; k < 8; k++) acc[k] += f * w[j + k];
                }
            }
#pragma unroll
            for (int k = 0; k < 8; k++) acc[k] = fmaxf(acc[k], 0.f);
        }

        float* dst = g_feat + ((v * 32 + c) * 384 + (y0 + yy)) * 384 + xb + xc * 8;
#pragma unroll
        for (int k = 0; k < 8; k++) dst[k] = acc[k];
    }
}

// ===========================================================================
// Kernel 2: channel normalization. One thread per (v, pixel).
// v=0 -> d_out (x1), v=1 -> in-place g_feat (x1_prev).
// ===========================================================================
__global__ void norm_kernel(float* __restrict__ out_x1)
{
    int idx = blockIdx.x * blockDim.x + threadIdx.x;
    if (idx >= 2 * 147456) return;
    int v   = idx / 147456;
    int pix = idx % 147456;
    float* base = g_feat + v * X1_ELEMS;

    float s = 0.f;
#pragma unroll
    for (int c = 0; c < 32; c++) s += base[c * 147456 + pix];
    float inv = 1.0f / (s + 2.2204460492503131e-16f);

    if (v == 0) {
#pragma unroll
        for (int c = 0; c < 32; c++)
            out_x1[c * 147456 + pix] = base[c * 147456 + pix] * inv;
    } else {
#pragma unroll
        for (int c = 0; c < 32; c++)
            base[c * 147456 + pix] *= inv;
    }
}

// ===========================================================================
// Kernel 3: normalized cross-correlation.
// Block = one (o = blockIdx.y, d = blockIdx.x) pair; 384 threads (368 active).
// Thread (h = tid%23, qc = tid/23): accumulates acc[w], w=0..22, over its
// q-chunk [24*qc, 24*qc+24) for all p (362 rows), using a 24-deep circular
// register window over x1_prev row (p+h). Invalid q>=362 killed via sC zeros.
// sP rows: rolling buffer of 23 rows of x1_prev[d], stride 409 (conflict-free).
// ===========================================================================
#define RSTRIDE 409

__global__ void __launch_bounds__(384) corr_kernel(const float* __restrict__ x1,
                                                   float* __restrict__ out)
{
    __shared__ float sP[23 * RSTRIDE];  // 9407 floats
    __shared__ float sC[384];

    const int o   = blockIdx.y;
    const int d   = blockIdx.x;
    const int tid = threadIdx.x;

    const float* C = x1 + o * 147456;                 // x1[o][y][x]
    const float* P = g_feat + X1_ELEMS + d * 147456;  // x1_prev[d][y][x]

    // Zero shared (pads must be 0)
    for (int i = tid; i < 23 * RSTRIDE; i += 384) sP[i] = 0.f;
    sC[tid] = 0.f;
    __syncthreads();

    // Preload x1_prev rows 0..21 into slots 0..21
    for (int e = tid; e < 22 * 384; e += 384) {
        int r  = e / 384;
        int cc = e % 384;
        sP[r * RSTRIDE + cc] = P[r * 384 + cc];
    }

    const bool active = tid < 368;
    const int  h  = active ? (tid % 23) : 0;
    const int  qc = active ? (tid / 23) : 0;
    const int  q0 = qc * 24;

    float acc[23];
#pragma unroll
    for (int w = 0; w < 23; w++) acc[w] = 0.f;

    for (int p = 0; p < 362; p++) {
        __syncthreads();  // prior compute done (and preload visible on p=0)

        // Load x1_prev row (p+22) into slot (p+22)%23 ; Crow = x1[o][11+p][11..372]
        {
            int r    = p + 22;                 // <= 383
            int slot = r % 23;
            sP[slot * RSTRIDE + tid] = P[r * 384 + tid];
            if (tid < 362) sC[tid] = C[(11 + p) * 384 + 11 + tid];
        }
        __syncthreads();

        if (active) {
            const float* Pr = sP + ((p + h) % 23) * RSTRIDE + q0;
            const float* Cr = sC + q0;
            float win[24];
#pragma unroll
            for (int k = 0; k < 23; k++) win[k] = Pr[k];
#pragma unroll
            for (int u = 0; u < 24; u++) {
                win[(u + 23) % 24] = Pr[u + 23];   // max index 46; pads are 0
                float cv = Cr[u];                  // 0 for q >= 362
#pragma unroll
                for (int w = 0; w < 23; w++)
                    acc[w] += cv * win[(u + w) % 24];
            }
        }
    }
    __syncthreads();

    // Reduce 16 q-chunks per (h,w) via shared (reuse sP: 368*23 = 8464 floats)
    float* red = sP;
    if (active) {
#pragma unroll
        for (int w = 0; w < 23; w++) red[tid * 23 + w] = acc[w];
    }
    __syncthreads();

    const float scale = 1.0f / 131044.0f;  // 362*362
    for (int i = tid; i < 529; i += 384) {
        int hh = i / 23, ww = i % 23;
        float s = 0.f;
#pragma unroll
        for (int q = 0; q < 16; q++) s += red[(q * 23 + hh) * 23 + ww];
        out[((o * 32 + d) * 23 + hh) * 23 + ww] = s * scale;
    }
}

// ===========================================================================
// Launch
// ===========================================================================
extern "C" void kernel_launch(void* const* d_in, const int* in_sizes, int n_in,
                              void* d_out, int out_size)
{
    const float* x  = (const float*)d_in[0];
    const float* xp = (const float*)d_in[1];
    float* out = (float*)d_out;

    void* aft = nullptr;
    void* afn = nullptr;
    cudaGetSymbolAddress(&aft, c_ft);
    cudaGetSymbolAddress(&afn, c_fn);
    cudaMemcpyAsync(aft, d_in[2], 5808 * sizeof(float), cudaMemcpyDeviceToDevice, 0);
    cudaMemcpyAsync(afn, d_in[3], 1936 * sizeof(float), cudaMemcpyDeviceToDevice, 0);

    dim3 g1(6, 48, 2);
    feat_kernel<<<g1, 256>>>(x, xp);

    norm_kernel<<<(2 * 147456 + 255) / 256, 256>>>(out);

    dim3 g3(32, 32);
    corr_kernel<<<g3, 384>>>(out, out + X1_ELEMS);
}

// round 3
// speedup vs baseline: 4.4070x; 4.4070x over previous
#include <cuda_runtime.h>
#include <cuda_bf16.h>
#include <cstdint>

// ---------------------------------------------------------------------------
// Net_22625887715641 on GB300 (sm_103a, compiled as compute_103 base ISA)
//
//   K1 feat_kernel : 11x11(x3) valid convs -> g_feat[2][32][384][384]
//   K2 norm_kernel : channel normalize; v=0 -> d_out (x1),
//                    v=1 in place + bf16 copy g_xp16 (implicit GEMM B, L2-resident)
//   K3 packA       : A[(o,w)][(p,q)] = masked/shifted x1 -> bf16 g_A[768][139008]
//   K4 gemm_kernel : mma.sync m16n8k16 bf16 GEMM 768x768x139008, split-K x4,
//                    cp.async 3-stage pipeline, atomicAdd into g_acc
//   K5 assemble    : g_acc -> x2 permute + scale
// ---------------------------------------------------------------------------

#define X1_ELEMS   (32 * 384 * 384)          // 4718592
#define GEMM_K     139008                    // 362*384
#define K_ITERS64  2172                      // GEMM_K / 64
#define SPLITS     4
#define IPS        543                       // K_ITERS64 / SPLITS (exact)

__device__ float   g_feat[2 * X1_ELEMS];
__device__ __align__(16) __nv_bfloat16 g_A[768 * GEMM_K];        // ~213MB
__device__ __align__(16) __nv_bfloat16 g_xp16[34 * 147456];      // bf16 x1_prev (+pad rows)
__device__ float   g_acc[768 * 768];
__constant__ float c_ft[16 * 3 * 11 * 11];
__constant__ float c_fn[16 * 11 * 11];

// ===================== PTX helpers ========================================
__device__ __forceinline__ uint32_t smem_u32(const void* p) {
    uint32_t a;
    asm("{ .reg .u64 t; cvta.to.shared.u64 t, %1; cvt.u32.u64 %0, t; }"
        : "=r"(a) : "l"(p));
    return a;
}
#define CP_ASYNC16(dst, src) \
    asm volatile("cp.async.cg.shared.global [%0], [%1], 16;" \
                 :: "r"(dst), "l"(src) : "memory")
#define CP_COMMIT() asm volatile("cp.async.commit_group;" ::: "memory")
#define CP_WAIT1()  asm volatile("cp.async.wait_group 1;" ::: "memory")

#define LDSM4(r0, r1, r2, r3, addr) \
    asm volatile("ldmatrix.sync.aligned.m8n8.x4.shared.b16 {%0,%1,%2,%3}, [%4];" \
                 : "=r"(r0), "=r"(r1), "=r"(r2), "=r"(r3) : "r"(addr))

#define MMA16816(D, a0, a1, a2, a3, b0, b1) \
    asm volatile("mma.sync.aligned.m16n8k16.row.col.f32.bf16.bf16.f32 " \
                 "{%0,%1,%2,%3}, {%4,%5,%6,%7}, {%8,%9}, {%0,%1,%2,%3};" \
                 : "+f"((D)[0]), "+f"((D)[1]), "+f"((D)[2]), "+f"((D)[3]) \
                 : "r"(a0), "r"(a1), "r"(a2), "r"(a3), "r"(b0), "r"(b1))

// ===========================================================================
// Kernel 1: features (unchanged, 118us)
// ===========================================================================
__global__ void __launch_bounds__(256) feat_kernel(const float* __restrict__ x0,
                                                   const float* __restrict__ x1in)
{
    __shared__ __align__(16) float s_in[3 * 18 * 76];
    const int v  = blockIdx.z;
    const float* src = v ? x1in : x0;
    const int y0 = blockIdx.y * 8;
    const int xb = blockIdx.x * 64;

    for (int e = threadIdx.x; e < 3 * 18 * 74; e += 256) {
        int t = e / (18 * 74);
        int rem = e % (18 * 74);
        int r = rem / 74;
        int cc = rem % 74;
        s_in[(t * 18 + r) * 76 + cc] = src[(t * 394 + (y0 + r)) * 394 + xb + cc];
    }
    __syncthreads();

    for (int it = 0; it < 8; it++) {
        int task = it * 256 + threadIdx.x;
        int c = task >> 6;
        int rem = task & 63;
        int yy = rem >> 3;
        int xc = rem & 7;

        float acc[8];
#pragma unroll
        for (int k = 0; k < 8; k++) acc[k] = 0.f;

        if (c < 16) {
            const float* fb = c_ft + c * 363;
            for (int t = 0; t < 3; t++) {
                for (int i = 0; i < 11; i++) {
                    const float4* rowp = reinterpret_cast<const float4*>(
                        &s_in[(t * 18 + (yy + i)) * 76 + xc * 8]);
                    float w[20];
#pragma unroll
                    for (int m = 0; m < 5; m++) {
                        float4 f4 = rowp[m];
                        w[4 * m] = f4.x; w[4 * m + 1] = f4.y;
                        w[4 * m + 2] = f4.z; w[4 * m + 3] = f4.w;
                    }
#pragma unroll
                    for (int j = 0; j < 11; j++) {
                        float f = fb[t * 121 + i * 11 + j];
#pragma unroll
                        for (int k = 0; k < 8; k++) acc[k] += f * w[j + k];
                    }
                }
            }
#pragma unroll
            for (int k = 0; k < 8; k++) acc[k] = fmaxf(acc[k], 0.f) * 0.5f;
        } else {
            const float* fb = c_fn + (c - 16) * 121;
            const int t = 2;
            for (int i = 0; i < 11; i++) {
                const float4* rowp = reinterpret_cast<const float4*>(
                    &s_in[(t * 18 + (yy + i)) * 76 + xc * 8]);
                float w[20];
#pragma unroll
                for (int m = 0; m < 5; m++) {
                    float4 f4 = rowp[m];
                    w[4 * m] = f4.x; w[4 * m + 1] = f4.y;
                    w[4 * m + 2] = f4.z; w[4 * m + 3] = f4.w;
                }
#pragma unroll
                for (int j = 0; j < 11; j++) {
                    float f = fb[i * 11 + j];
#pragma unroll
                    for (int k = 0; k < 8; k++) acc[k] += f * w[j + k];
                }
            }
#pragma unroll
            for (int k = 0; k < 8; k++) acc[k] = fmaxf(acc[k], 0.f);
        }

        float* dst = g_feat + ((v * 32 + c) * 384 + (y0 + yy)) * 384 + xb + xc * 8;
#pragma unroll
        for (int k = 0; k < 8; k++) dst[k] = acc[k];
    }
}

// ===========================================================================
// Kernel 2: channel normalization (+ bf16 emission of x1_prev)
// ===========================================================================
__global__ void norm_kernel(float* __restrict__ out_x1)
{
    int idx = blockIdx.x * blockDim.x + threadIdx.x;
    if (idx >= 2 * 147456) return;
    int v = idx / 147456;
    int pix = idx % 147456;
    float* base = g_feat + v * X1_ELEMS;

    float s = 0.f;
#pragma unroll
    for (int c = 0; c < 32; c++) s += base[c * 147456 + pix];
    float inv = 1.0f / (s + 2.2204460492503131e-16f);

    if (v == 0) {
#pragma unroll
        for (int c = 0; c < 32; c++)
            out_x1[c * 147456 + pix] = base[c * 147456 + pix] * inv;
    } else {
#pragma unroll
        for (int c = 0; c < 32; c++) {
            float val = base[c * 147456 + pix] * inv;
            base[c * 147456 + pix] = val;
            g_xp16[c * 147456 + pix] = __float2bfloat16(val);
        }
    }
}

// ===========================================================================
// Kernel 3: pack A (shifted/masked x1) to bf16; rows 736..767 zero.
// A[r=(o,w)][p*384+q] = (w <= q < 362+w) ? x1[o, 11+p, 11+q-w] : 0
// ===========================================================================
__global__ void __launch_bounds__(256) packA_kernel(const float* __restrict__ x1)
{
    const int CH = GEMM_K / 8;  // 17376
    int idx = blockIdx.x * 256 + threadIdx.x;
    if (idx >= 768 * CH) return;
    int r  = idx / CH;
    int c8 = idx % CH;
    int K0 = c8 * 8;
    int p  = K0 / 384;
    int q  = K0 % 384;

    __nv_bfloat16 v[8];
    if (r < 736) {
        int o = r / 23, w = r % 23;
        const float* src = x1 + o * 147456 + (11 + p) * 384 + 11 - w;
#pragma unroll
        for (int k = 0; k < 8; k++) {
            int qq = q + k;
            float f = (qq >= w && qq < 362 + w) ? src[qq] : 0.f;
            v[k] = __float2bfloat16(f);
        }
    } else {
#pragma unroll
        for (int k = 0; k < 8; k++) v[k] = __float2bfloat16(0.f);
    }
    uint4 pk;
    uint16_t* b = reinterpret_cast<uint16_t*>(&pk);
#pragma unroll
    for (int k = 0; k < 8; k++) b[k] = *reinterpret_cast<uint16_t*>(&v[k]);
    reinterpret_cast<uint4*>(g_A)[idx] = pk;
}

// ===========================================================================
// Kernel 4: mma.sync bf16 GEMM. grid (Nt:6, Mt:6, split:4), 256 threads.
// CTA tile 128x128, kc=64, 3-stage cp.async pipeline.
// smem: 3 x A[128][72]bf16 + 3 x B[128][72]bf16 = 110592 B (stride 144 B).
// ===========================================================================
#define TILE_BYTES 18432            // 128*144
#define GEMM_SMEM  (6 * TILE_BYTES)

__global__ void __launch_bounds__(256, 1) gemm_kernel()
{
    extern __shared__ char smem[];
    const uint32_t sb = smem_u32(smem);
    const int tid = threadIdx.x;
    const int lane = tid & 31, wid = tid >> 5;
    const int Nt = blockIdx.x, Mt = blockIdx.y, sp = blockIdx.z;
    const int wm = wid & 3, wn = wid >> 2;   // warp tile: rows wm*32, cols wn*64
    const int g = lane >> 2, t4 = lane & 3;

    uint32_t bufA[3], bufB[3];
#pragma unroll
    for (int i = 0; i < 3; i++) {
        bufA[i] = sb + i * TILE_BYTES;
        bufB[i] = sb + (3 + i) * TILE_BYTES;
    }

    // ---- cp.async source/dest mapping: 4 chunks (16B) per thread per tile ----
    const int lr = tid >> 3;         // 0..31
    const int lc = tid & 7;          // 0..7
    const __nv_bfloat16* gA0 = g_A + (size_t)(Mt * 128 + lr) * GEMM_K + lc * 8;
    const __nv_bfloat16* gB0[4];
#pragma unroll
    for (int j = 0; j < 4; j++) {
        int n = Nt * 128 + lr + 32 * j;
        gB0[j] = g_xp16 + (size_t)(n / 23) * 147456 + (n % 23) * 384 + lc * 8;
    }
    const uint32_t dOff = (uint32_t)(lr * 144 + lc * 16);

    const int k0 = sp * IPS, k1 = k0 + IPS;

#define LOAD_TILE(kt, b) do {                                                  \
        size_t _ko = (size_t)(kt) * 64;                                        \
        _Pragma("unroll")                                                      \
        for (int _j = 0; _j < 4; _j++) {                                       \
            CP_ASYNC16(bufA[b] + dOff + _j * (32 * 144),                       \
                       gA0 + _ko + (size_t)_j * 32 * GEMM_K);                  \
            CP_ASYNC16(bufB[b] + dOff + _j * (32 * 144), gB0[_j] + _ko);       \
        }                                                                      \
    } while (0)

    LOAD_TILE(k0, k0 % 3);       CP_COMMIT();
    LOAD_TILE(k0 + 1, (k0 + 1) % 3); CP_COMMIT();

    float acc[2][8][4];
#pragma unroll
    for (int mt = 0; mt < 2; mt++)
#pragma unroll
        for (int nt = 0; nt < 8; nt++)
#pragma unroll
            for (int e = 0; e < 4; e++) acc[mt][nt][e] = 0.f;

    // ---- per-lane ldmatrix offsets (bytes) ----
    const int matq = lane >> 3, rin = lane & 7;
    const uint32_t offA = (uint32_t)((((matq & 1) * 8 + rin) * 144) + (matq >> 1) * 16);
    const uint32_t offB = (uint32_t)((((matq >> 1) * 8 + rin) * 144) + (matq & 1) * 16);
    const uint32_t aRow = (uint32_t)(wm * 32) * 144;
    const uint32_t bRow = (uint32_t)(wn * 64) * 144;

    for (int kt = k0; kt < k1; kt++) {
        CP_WAIT1();          // tile kt complete (last committed = kt+1)
        __syncthreads();     // visibility + all warps done with buf[(kt+2)%3]
        if (kt + 2 < k1) LOAD_TILE(kt + 2, (kt + 2) % 3);
        CP_COMMIT();         // always commit (possibly empty group)

        const uint32_t bA = bufA[kt % 3], bB = bufB[kt % 3];
#pragma unroll
        for (int ks = 0; ks < 4; ks++) {
            uint32_t a[2][4];
#pragma unroll
            for (int mt = 0; mt < 2; mt++)
                LDSM4(a[mt][0], a[mt][1], a[mt][2], a[mt][3],
                      bA + aRow + mt * (16 * 144) + ks * 32 + offA);
#pragma unroll
            for (int p = 0; p < 4; p++) {
                uint32_t b0, b1, b2, b3;
                LDSM4(b0, b1, b2, b3, bB + bRow + p * (16 * 144) + ks * 32 + offB);
#pragma unroll
                for (int mt = 0; mt < 2; mt++) {
                    MMA16816(acc[mt][2 * p],     a[mt][0], a[mt][1], a[mt][2], a[mt][3], b0, b1);
                    MMA16816(acc[mt][2 * p + 1], a[mt][0], a[mt][1], a[mt][2], a[mt][3], b2, b3);
                }
            }
        }
    }

    // ---- epilogue: atomicAdd into g_acc (split-K reduction) ----
    const int row0 = Mt * 128 + wm * 32;
    const int col0 = Nt * 128 + wn * 64;
#pragma unroll
    for (int mt = 0; mt < 2; mt++) {
        int r_lo = row0 + mt * 16 + g;
        int r_hi = r_lo + 8;
#pragma unroll
        for (int nt = 0; nt < 8; nt++) {
            int c = col0 + nt * 8 + 2 * t4;
            bool c0ok = (c < 736), c1ok = (c + 1 < 736);
            if (r_lo < 736) {
                if (c0ok) atomicAdd(&g_acc[r_lo * 768 + c],     acc[mt][nt][0]);
                if (c1ok) atomicAdd(&g_acc[r_lo * 768 + c + 1], acc[mt][nt][1]);
            }
            if (r_hi < 736) {
                if (c0ok) atomicAdd(&g_acc[r_hi * 768 + c],     acc[mt][nt][2]);
                if (c1ok) atomicAdd(&g_acc[r_hi * 768 + c + 1], acc[mt][nt][3]);
            }
        }
    }
#undef LOAD_TILE
}

// ===========================================================================
// Kernel 5: assemble x2 from g_acc with permutation + scale
// ===========================================================================
__global__ void assemble_kernel(float* __restrict__ out_x2)
{
    int i = blockIdx.x * 256 + threadIdx.x;
    if (i >= 32 * 32 * 23 * 23) return;
    int w = i % 23;
    int t = i / 23;
    int h = t % 23; t /= 23;
    int d = t % 32;
    int o = t / 32;
    out_x2[i] = g_acc[(o * 23 + w) * 768 + (d * 23 + h)] * (1.0f / 131044.0f);
}

// ===========================================================================
// Launch
// ===========================================================================
extern "C" void kernel_launch(void* const* d_in, const int* in_sizes, int n_in,
                              void* d_out, int out_size)
{
    const float* x  = (const float*)d_in[0];
    const float* xp = (const float*)d_in[1];
    float* out = (float*)d_out;

    void *aft = nullptr, *afn = nullptr, *aacc = nullptr;
    cudaGetSymbolAddress(&aft, c_ft);
    cudaGetSymbolAddress(&afn, c_fn);
    cudaGetSymbolAddress(&aacc, g_acc);
    cudaMemcpyAsync(aft, d_in[2], 5808 * sizeof(float), cudaMemcpyDeviceToDevice, 0);
    cudaMemcpyAsync(afn, d_in[3], 1936 * sizeof(float), cudaMemcpyDeviceToDevice, 0);
    cudaMemsetAsync(aacc, 0, 768 * 768 * sizeof(float), 0);

    dim3 g1(6, 48, 2);
    feat_kernel<<<g1, 256>>>(x, xp);

    norm_kernel<<<(2 * 147456 + 255) / 256, 256>>>(out);

    packA_kernel<<<(768 * (GEMM_K / 8) + 255) / 256, 256>>>(out);

    static bool attr_set = false;
    if (!attr_set) {
        cudaFuncSetAttribute(gemm_kernel, cudaFuncAttributeMaxDynamicSharedMemorySize,
                             GEMM_SMEM);
        attr_set = true;
    }
    dim3 g4(6, 6, SPLITS);
    gemm_kernel<<<g4, 256, GEMM_SMEM>>>();

    assemble_kernel<<<(32 * 32 * 23 * 23 + 255) / 256, 256>>>(out + X1_ELEMS);
}

// round 4
// speedup vs baseline: 4.5009x; 1.0213x over previous
#include <cuda_runtime.h>
#include <cuda_bf16.h>
#include <cstdint>

// ---------------------------------------------------------------------------
// Net_22625887715641 on GB300 (sm_103a, compiled as compute_103 base ISA)
//
//   K1 feat_kernel : 11x11(x3) valid convs -> g_feat[2][32][384][384]
//   K2 norm_kernel : channel normalize; v=0 -> d_out (x1),
//                    v=1 in place + bf16 copy g_xp16 (implicit GEMM B)
//   K3 packA       : A[(o,w)][(p,q)] = masked/shifted x1 -> bf16 g_A
//   K4 gemm_kernel : mma.sync m16n8k16 bf16 GEMM 768x768x139008, split-K x4,
//                    4-stage cp.async + double-buffered ldmatrix fragments
//   K5 assemble    : g_acc -> x2 permute + scale
// ---------------------------------------------------------------------------

#define X1_ELEMS   (32 * 384 * 384)          // 4718592
#define GEMM_K     139008                    // 362*384
#define K_ITERS64  2172                      // GEMM_K / 64
#define SPLITS     4
#define IPS        543                       // K_ITERS64 / SPLITS (exact)

__device__ float   g_feat[2 * X1_ELEMS];
__device__ __align__(16) __nv_bfloat16 g_A[768 * GEMM_K];        // ~213MB
__device__ __align__(16) __nv_bfloat16 g_xp16[34 * 147456];
__device__ float   g_acc[768 * 768];
__constant__ float c_ft[16 * 3 * 11 * 11];
__constant__ float c_fn[16 * 11 * 11];

// ===================== PTX helpers ========================================
__device__ __forceinline__ uint32_t smem_u32(const void* p) {
    uint32_t a;
    asm("{ .reg .u64 t; cvta.to.shared.u64 t, %1; cvt.u32.u64 %0, t; }"
        : "=r"(a) : "l"(p));
    return a;
}
#define CP_ASYNC16(dst, src) \
    asm volatile("cp.async.cg.shared.global [%0], [%1], 16;" \
                 :: "r"(dst), "l"(src) : "memory")
#define CP_COMMIT() asm volatile("cp.async.commit_group;" ::: "memory")
#define CP_WAIT2()  asm volatile("cp.async.wait_group 2;" ::: "memory")

#define LDSM4(r0, r1, r2, r3, addr) \
    asm volatile("ldmatrix.sync.aligned.m8n8.x4.shared.b16 {%0,%1,%2,%3}, [%4];" \
                 : "=r"(r0), "=r"(r1), "=r"(r2), "=r"(r3) : "r"(addr))

#define MMA16816(D, a0, a1, a2, a3, b0, b1) \
    asm volatile("mma.sync.aligned.m16n8k16.row.col.f32.bf16.bf16.f32 " \
                 "{%0,%1,%2,%3}, {%4,%5,%6,%7}, {%8,%9}, {%0,%1,%2,%3};" \
                 : "+f"((D)[0]), "+f"((D)[1]), "+f"((D)[2]), "+f"((D)[3]) \
                 : "r"(a0), "r"(a1), "r"(a2), "r"(a3), "r"(b0), "r"(b1))

// ===========================================================================
// Kernel 1: features (unchanged, 118us)
// ===========================================================================
__global__ void __launch_bounds__(256) feat_kernel(const float* __restrict__ x0,
                                                   const float* __restrict__ x1in)
{
    __shared__ __align__(16) float s_in[3 * 18 * 76];
    const int v  = blockIdx.z;
    const float* src = v ? x1in : x0;
    const int y0 = blockIdx.y * 8;
    const int xb = blockIdx.x * 64;

    for (int e = threadIdx.x; e < 3 * 18 * 74; e += 256) {
        int t = e / (18 * 74);
        int rem = e % (18 * 74);
        int r = rem / 74;
        int cc = rem % 74;
        s_in[(t * 18 + r) * 76 + cc] = src[(t * 394 + (y0 + r)) * 394 + xb + cc];
    }
    __syncthreads();

    for (int it = 0; it < 8; it++) {
        int task = it * 256 + threadIdx.x;
        int c = task >> 6;
        int rem = task & 63;
        int yy = rem >> 3;
        int xc = rem & 7;

        float acc[8];
#pragma unroll
        for (int k = 0; k < 8; k++) acc[k] = 0.f;

        if (c < 16) {
            const float* fb = c_ft + c * 363;
            for (int t = 0; t < 3; t++) {
                for (int i = 0; i < 11; i++) {
                    const float4* rowp = reinterpret_cast<const float4*>(
                        &s_in[(t * 18 + (yy + i)) * 76 + xc * 8]);
                    float w[20];
#pragma unroll
                    for (int m = 0; m < 5; m++) {
                        float4 f4 = rowp[m];
                        w[4 * m] = f4.x; w[4 * m + 1] = f4.y;
                        w[4 * m + 2] = f4.z; w[4 * m + 3] = f4.w;
                    }
#pragma unroll
                    for (int j = 0; j < 11; j++) {
                        float f = fb[t * 121 + i * 11 + j];
#pragma unroll
                        for (int k = 0; k < 8; k++) acc[k] += f * w[j + k];
                    }
                }
            }
#pragma unroll
            for (int k = 0; k < 8; k++) acc[k] = fmaxf(acc[k], 0.f) * 0.5f;
        } else {
            const float* fb = c_fn + (c - 16) * 121;
            const int t = 2;
            for (int i = 0; i < 11; i++) {
                const float4* rowp = reinterpret_cast<const float4*>(
                    &s_in[(t * 18 + (yy + i)) * 76 + xc * 8]);
                float w[20];
#pragma unroll
                for (int m = 0; m < 5; m++) {
                    float4 f4 = rowp[m];
                    w[4 * m] = f4.x; w[4 * m + 1] = f4.y;
                    w[4 * m + 2] = f4.z; w[4 * m + 3] = f4.w;
                }
#pragma unroll
                for (int j = 0; j < 11; j++) {
                    float f = fb[i * 11 + j];
#pragma unroll
                    for (int k = 0; k < 8; k++) acc[k] += f * w[j + k];
                }
            }
#pragma unroll
            for (int k = 0; k < 8; k++) acc[k] = fmaxf(acc[k], 0.f);
        }

        float* dst = g_feat + ((v * 32 + c) * 384 + (y0 + yy)) * 384 + xb + xc * 8;
#pragma unroll
        for (int k = 0; k < 8; k++) dst[k] = acc[k];
    }
}

// ===========================================================================
// Kernel 2: channel normalization (+ bf16 emission of x1_prev)
// ===========================================================================
__global__ void norm_kernel(float* __restrict__ out_x1)
{
    int idx = blockIdx.x * blockDim.x + threadIdx.x;
    if (idx >= 2 * 147456) return;
    int v = idx / 147456;
    int pix = idx % 147456;
    float* base = g_feat + v * X1_ELEMS;

    float s = 0.f;
#pragma unroll
    for (int c = 0; c < 32; c++) s += base[c * 147456 + pix];
    float inv = 1.0f / (s + 2.2204460492503131e-16f);

    if (v == 0) {
#pragma unroll
        for (int c = 0; c < 32; c++)
            out_x1[c * 147456 + pix] = base[c * 147456 + pix] * inv;
    } else {
#pragma unroll
        for (int c = 0; c < 32; c++) {
            float val = base[c * 147456 + pix] * inv;
            base[c * 147456 + pix] = val;
            g_xp16[c * 147456 + pix] = __float2bfloat16(val);
        }
    }
}

// ===========================================================================
// Kernel 3: pack A (shifted/masked x1) to bf16; rows 736..767 zero.
// ===========================================================================
__global__ void __launch_bounds__(256) packA_kernel(const float* __restrict__ x1)
{
    const int CH = GEMM_K / 8;  // 17376
    int idx = blockIdx.x * 256 + threadIdx.x;
    if (idx >= 768 * CH) return;
    int r  = idx / CH;
    int c8 = idx % CH;
    int K0 = c8 * 8;
    int p  = K0 / 384;
    int q  = K0 % 384;

    __nv_bfloat16 v[8];
    if (r < 736) {
        int o = r / 23, w = r % 23;
        const float* src = x1 + o * 147456 + (11 + p) * 384 + 11 - w;
#pragma unroll
        for (int k = 0; k < 8; k++) {
            int qq = q + k;
            float f = (qq >= w && qq < 362 + w) ? src[qq] : 0.f;
            v[k] = __float2bfloat16(f);
        }
    } else {
#pragma unroll
        for (int k = 0; k < 8; k++) v[k] = __float2bfloat16(0.f);
    }
    uint4 pk;
    uint16_t* b = reinterpret_cast<uint16_t*>(&pk);
#pragma unroll
    for (int k = 0; k < 8; k++) b[k] = *reinterpret_cast<uint16_t*>(&v[k]);
    reinterpret_cast<uint4*>(g_A)[idx] = pk;
}

// ===========================================================================
// Kernel 4: mma.sync bf16 GEMM. grid (Nt:6, Mt:6, split:4), 256 threads.
// CTA tile 128x128, kc=64, 4-stage cp.async + double-buffered fragments.
// smem: 4 x A[128][72]bf16 + 4 x B[128][72]bf16 = 147456 B (stride 144 B).
// ===========================================================================
#define TILE_BYTES 18432            // 128*144
#define GEMM_SMEM  (8 * TILE_BYTES) // 147456

__global__ void __launch_bounds__(256, 1) gemm_kernel()
{
    extern __shared__ char smem[];
    const uint32_t sb = smem_u32(smem);
    const int tid = threadIdx.x;
    const int lane = tid & 31, wid = tid >> 5;
    const int Nt = blockIdx.x, Mt = blockIdx.y, sp = blockIdx.z;
    const int wm = wid & 3, wn = wid >> 2;   // warp tile: rows wm*32, cols wn*64
    const int g = lane >> 2, t4 = lane & 3;

    uint32_t bufA[4], bufB[4];
#pragma unroll
    for (int i = 0; i < 4; i++) {
        bufA[i] = sb + i * TILE_BYTES;
        bufB[i] = sb + (4 + i) * TILE_BYTES;
    }

    // ---- cp.async mapping: 4 chunks (16B) per thread per tile ----
    const int lr = tid >> 3;         // 0..31
    const int lc = tid & 7;          // 0..7
    const __nv_bfloat16* gA0 = g_A + (size_t)(Mt * 128 + lr) * GEMM_K + lc * 8;
    const __nv_bfloat16* gB0[4];
#pragma unroll
    for (int j = 0; j < 4; j++) {
        int n = Nt * 128 + lr + 32 * j;
        gB0[j] = g_xp16 + (size_t)(n / 23) * 147456 + (n % 23) * 384 + lc * 8;
    }
    const uint32_t dOff = (uint32_t)(lr * 144 + lc * 16);

    const int k0 = sp * IPS, k1 = k0 + IPS;

#define LOAD_TILE(kt, b) do {                                                  \
        size_t _ko = (size_t)(kt) * 64;                                        \
        _Pragma("unroll")                                                      \
        for (int _j = 0; _j < 4; _j++) {                                       \
            CP_ASYNC16(bufA[b] + dOff + _j * (32 * 144),                       \
                       gA0 + _ko + (size_t)_j * 32 * GEMM_K);                  \
            CP_ASYNC16(bufB[b] + dOff + _j * (32 * 144), gB0[_j] + _ko);       \
        }                                                                      \
    } while (0)

    LOAD_TILE(k0,     (k0) & 3);     CP_COMMIT();
    LOAD_TILE(k0 + 1, (k0 + 1) & 3); CP_COMMIT();
    LOAD_TILE(k0 + 2, (k0 + 2) & 3); CP_COMMIT();

    float acc[2][8][4];
#pragma unroll
    for (int mt = 0; mt < 2; mt++)
#pragma unroll
        for (int nt = 0; nt < 8; nt++)
#pragma unroll
            for (int e = 0; e < 4; e++) acc[mt][nt][e] = 0.f;

    // ---- per-lane ldmatrix offsets (bytes) ----
    const int matq = lane >> 3, rin = lane & 7;
    const uint32_t offA = (uint32_t)((((matq & 1) * 8 + rin) * 144) + (matq >> 1) * 16);
    const uint32_t offB = (uint32_t)((((matq >> 1) * 8 + rin) * 144) + (matq & 1) * 16);
    const uint32_t aRow = (uint32_t)(wm * 32) * 144;
    const uint32_t bRow = (uint32_t)(wn * 64) * 144;

    // fragment double buffers
    uint32_t Af[2][2][4], Bf[2][4][4];

#define LDS_ALL(fb, bA, bB, ks) do {                                           \
        _Pragma("unroll")                                                      \
        for (int _mt = 0; _mt < 2; _mt++)                                      \
            LDSM4(Af[fb][_mt][0], Af[fb][_mt][1], Af[fb][_mt][2], Af[fb][_mt][3], \
                  (bA) + aRow + _mt * (16 * 144) + (ks) * 32 + offA);          \
        _Pragma("unroll")                                                      \
        for (int _p = 0; _p < 4; _p++)                                         \
            LDSM4(Bf[fb][_p][0], Bf[fb][_p][1], Bf[fb][_p][2], Bf[fb][_p][3],  \
                  (bB) + bRow + _p * (16 * 144) + (ks) * 32 + offB);           \
    } while (0)

#define MMA_ALL(fb) do {                                                       \
        _Pragma("unroll")                                                      \
        for (int _p = 0; _p < 4; _p++) {                                       \
            _Pragma("unroll")                                                  \
            for (int _mt = 0; _mt < 2; _mt++) {                                \
                MMA16816(acc[_mt][2 * _p],     Af[fb][_mt][0], Af[fb][_mt][1], \
                         Af[fb][_mt][2], Af[fb][_mt][3], Bf[fb][_p][0], Bf[fb][_p][1]); \
                MMA16816(acc[_mt][2 * _p + 1], Af[fb][_mt][0], Af[fb][_mt][1], \
                         Af[fb][_mt][2], Af[fb][_mt][3], Bf[fb][_p][2], Bf[fb][_p][3]); \
            }                                                                  \
        }                                                                      \
    } while (0)

    for (int kt = k0; kt < k1; kt++) {
        CP_WAIT2();          // tile kt complete (3 ahead committed)
        __syncthreads();     // all warps done with buf[(kt+3)&3]'s previous life
        if (kt + 3 < k1) LOAD_TILE(kt + 3, (kt + 3) & 3);
        CP_COMMIT();         // always commit (possibly empty group)

        const uint32_t bA = bufA[kt & 3], bB = bufB[kt & 3];

        LDS_ALL(0, bA, bB, 0);
#pragma unroll
        for (int ks = 0; ks < 4; ks++) {
            const int cur = ks & 1, nxt = cur ^ 1;
            if (ks < 3) {
                if (nxt) LDS_ALL(1, bA, bB, ks + 1);
                else     LDS_ALL(0, bA, bB, ks + 1);
            }
            if (cur) MMA_ALL(1);
            else     MMA_ALL(0);
        }
    }

    // ---- epilogue: atomicAdd into g_acc (split-K reduction) ----
    const int row0 = Mt * 128 + wm * 32;
    const int col0 = Nt * 128 + wn * 64;
#pragma unroll
    for (int mt = 0; mt < 2; mt++) {
        int r_lo = row0 + mt * 16 + g;
        int r_hi = r_lo + 8;
#pragma unroll
        for (int nt = 0; nt < 8; nt++) {
            int c = col0 + nt * 8 + 2 * t4;
            bool c0ok = (c < 736), c1ok = (c + 1 < 736);
            if (r_lo < 736) {
                if (c0ok) atomicAdd(&g_acc[r_lo * 768 + c],     acc[mt][nt][0]);
                if (c1ok) atomicAdd(&g_acc[r_lo * 768 + c + 1], acc[mt][nt][1]);
            }
            if (r_hi < 736) {
                if (c0ok) atomicAdd(&g_acc[r_hi * 768 + c],     acc[mt][nt][2]);
                if (c1ok) atomicAdd(&g_acc[r_hi * 768 + c + 1], acc[mt][nt][3]);
            }
        }
    }
#undef LOAD_TILE
#undef LDS_ALL
#undef MMA_ALL
}

// ===========================================================================
// Kernel 5: assemble x2 from g_acc with permutation + scale
// ===========================================================================
__global__ void assemble_kernel(float* __restrict__ out_x2)
{
    int i = blockIdx.x * 256 + threadIdx.x;
    if (i >= 32 * 32 * 23 * 23) return;
    int w = i % 23;
    int t = i / 23;
    int h = t % 23; t /= 23;
    int d = t % 32;
    int o = t / 32;
    out_x2[i] = g_acc[(o * 23 + w) * 768 + (d * 23 + h)] * (1.0f / 131044.0f);
}

// ===========================================================================
// Launch
// ===========================================================================
extern "C" void kernel_launch(void* const* d_in, const int* in_sizes, int n_in,
                              void* d_out, int out_size)
{
    const float* x  = (const float*)d_in[0];
    const float* xp = (const float*)d_in[1];
    float* out = (float*)d_out;

    void *aft = nullptr, *afn = nullptr, *aacc = nullptr;
    cudaGetSymbolAddress(&aft, c_ft);
    cudaGetSymbolAddress(&afn, c_fn);
    cudaGetSymbolAddress(&aacc, g_acc);
    cudaMemcpyAsync(aft, d_in[2], 5808 * sizeof(float), cudaMemcpyDeviceToDevice, 0);
    cudaMemcpyAsync(afn, d_in[3], 1936 * sizeof(float), cudaMemcpyDeviceToDevice, 0);
    cudaMemsetAsync(aacc, 0, 768 * 768 * sizeof(float), 0);

    dim3 g1(6, 48, 2);
    feat_kernel<<<g1, 256>>>(x, xp);

    norm_kernel<<<(2 * 147456 + 255) / 256, 256>>>(out);

    packA_kernel<<<(768 * (GEMM_K / 8) + 255) / 256, 256>>>(out);

    static bool attr_set = false;
    if (!attr_set) {
        cudaFuncSetAttribute(gemm_kernel, cudaFuncAttributeMaxDynamicSharedMemorySize,
                             GEMM_SMEM);
        attr_set = true;
    }
    dim3 g4(6, 6, SPLITS);
    gemm_kernel<<<g4, 256, GEMM_SMEM>>>();

    assemble_kernel<<<(32 * 32 * 23 * 23 + 255) / 256, 256>>>(out + X1_ELEMS);
}

// round 5
// speedup vs baseline: 4.9516x; 1.1001x over previous
#include <cuda_runtime.h>
#include <cuda_bf16.h>
#include <cstdint>

// ---------------------------------------------------------------------------
// Net_22625887715641 on GB300 (sm_103a, compiled as compute_103 base ISA)
//
//   K1 feat_kernel : 11x11(x3) valid convs -> g_feat[2][32][384][384]
//   K2 norm_kernel : channel normalize; v=0 -> d_out (x1),
//                    v=1 in place + bf16 copy g_xp16 (implicit GEMM B)
//   K3 packA       : A[(o,w)][(p,q)] = masked/shifted x1 -> bf16 g_A
//   K4 gemm_kernel : mma.sync m16n8k16 bf16 GEMM 768x768x139008, split-K x4,
//                    512 threads (16 warps, 32x32 warp tiles), 4-stage cp.async,
//                    cross-iteration ldmatrix fragment pipeline
//   K5 assemble    : g_acc -> x2 permute + scale
// ---------------------------------------------------------------------------

#define X1_ELEMS   (32 * 384 * 384)          // 4718592
#define GEMM_K     139008                    // 362*384
#define K_ITERS64  2172                      // GEMM_K / 64
#define SPLITS     4
#define IPS        543                       // K_ITERS64 / SPLITS (exact)

__device__ float   g_feat[2 * X1_ELEMS];
__device__ __align__(16) __nv_bfloat16 g_A[768 * GEMM_K];        // ~213MB
__device__ __align__(16) __nv_bfloat16 g_xp16[34 * 147456];
__device__ float   g_acc[768 * 768];
__constant__ float c_ft[16 * 3 * 11 * 11];
__constant__ float c_fn[16 * 11 * 11];

// ===================== PTX helpers ========================================
__device__ __forceinline__ uint32_t smem_u32(const void* p) {
    uint32_t a;
    asm("{ .reg .u64 t; cvta.to.shared.u64 t, %1; cvt.u32.u64 %0, t; }"
        : "=r"(a) : "l"(p));
    return a;
}
#define CP_ASYNC16(dst, src) \
    asm volatile("cp.async.cg.shared.global [%0], [%1], 16;" \
                 :: "r"(dst), "l"(src) : "memory")
#define CP_COMMIT() asm volatile("cp.async.commit_group;" ::: "memory")
#define CP_WAIT1()  asm volatile("cp.async.wait_group 1;" ::: "memory")
#define CP_WAIT2()  asm volatile("cp.async.wait_group 2;" ::: "memory")

#define LDSM4(r0, r1, r2, r3, addr) \
    asm volatile("ldmatrix.sync.aligned.m8n8.x4.shared.b16 {%0,%1,%2,%3}, [%4];" \
                 : "=r"(r0), "=r"(r1), "=r"(r2), "=r"(r3) : "r"(addr))

#define MMA16816(D, a0, a1, a2, a3, b0, b1) \
    asm volatile("mma.sync.aligned.m16n8k16.row.col.f32.bf16.bf16.f32 " \
                 "{%0,%1,%2,%3}, {%4,%5,%6,%7}, {%8,%9}, {%0,%1,%2,%3};" \
                 : "+f"((D)[0]), "+f"((D)[1]), "+f"((D)[2]), "+f"((D)[3]) \
                 : "r"(a0), "r"(a1), "r"(a2), "r"(a3), "r"(b0), "r"(b1))

// ===========================================================================
// Kernel 1: features (unchanged, 118us)
// ===========================================================================
__global__ void __launch_bounds__(256) feat_kernel(const float* __restrict__ x0,
                                                   const float* __restrict__ x1in)
{
    __shared__ __align__(16) float s_in[3 * 18 * 76];
    const int v  = blockIdx.z;
    const float* src = v ? x1in : x0;
    const int y0 = blockIdx.y * 8;
    const int xb = blockIdx.x * 64;

    for (int e = threadIdx.x; e < 3 * 18 * 74; e += 256) {
        int t = e / (18 * 74);
        int rem = e % (18 * 74);
        int r = rem / 74;
        int cc = rem % 74;
        s_in[(t * 18 + r) * 76 + cc] = src[(t * 394 + (y0 + r)) * 394 + xb + cc];
    }
    __syncthreads();

    for (int it = 0; it < 8; it++) {
        int task = it * 256 + threadIdx.x;
        int c = task >> 6;
        int rem = task & 63;
        int yy = rem >> 3;
        int xc = rem & 7;

        float acc[8];
#pragma unroll
        for (int k = 0; k < 8; k++) acc[k] = 0.f;

        if (c < 16) {
            const float* fb = c_ft + c * 363;
            for (int t = 0; t < 3; t++) {
                for (int i = 0; i < 11; i++) {
                    const float4* rowp = reinterpret_cast<const float4*>(
                        &s_in[(t * 18 + (yy + i)) * 76 + xc * 8]);
                    float w[20];
#pragma unroll
                    for (int m = 0; m < 5; m++) {
                        float4 f4 = rowp[m];
                        w[4 * m] = f4.x; w[4 * m + 1] = f4.y;
                        w[4 * m + 2] = f4.z; w[4 * m + 3] = f4.w;
                    }
#pragma unroll
                    for (int j = 0; j < 11; j++) {
                        float f = fb[t * 121 + i * 11 + j];
#pragma unroll
                        for (int k = 0; k < 8; k++) acc[k] += f * w[j + k];
                    }
                }
            }
#pragma unroll
            for (int k = 0; k < 8; k++) acc[k] = fmaxf(acc[k], 0.f) * 0.5f;
        } else {
            const float* fb = c_fn + (c - 16) * 121;
            const int t = 2;
            for (int i = 0; i < 11; i++) {
                const float4* rowp = reinterpret_cast<const float4*>(
                    &s_in[(t * 18 + (yy + i)) * 76 + xc * 8]);
                float w[20];
#pragma unroll
                for (int m = 0; m < 5; m++) {
                    float4 f4 = rowp[m];
                    w[4 * m] = f4.x; w[4 * m + 1] = f4.y;
                    w[4 * m + 2] = f4.z; w[4 * m + 3] = f4.w;
                }
#pragma unroll
                for (int j = 0; j < 11; j++) {
                    float f = fb[i * 11 + j];
#pragma unroll
                    for (int k = 0; k < 8; k++) acc[k] += f * w[j + k];
                }
            }
#pragma unroll
            for (int k = 0; k < 8; k++) acc[k] = fmaxf(acc[k], 0.f);
        }

        float* dst = g_feat + ((v * 32 + c) * 384 + (y0 + yy)) * 384 + xb + xc * 8;
#pragma unroll
        for (int k = 0; k < 8; k++) dst[k] = acc[k];
    }
}

// ===========================================================================
// Kernel 2: channel normalization (+ bf16 emission of x1_prev)
// ===========================================================================
__global__ void norm_kernel(float* __restrict__ out_x1)
{
    int idx = blockIdx.x * blockDim.x + threadIdx.x;
    if (idx >= 2 * 147456) return;
    int v = idx / 147456;
    int pix = idx % 147456;
    float* base = g_feat + v * X1_ELEMS;

    float s = 0.f;
#pragma unroll
    for (int c = 0; c < 32; c++) s += base[c * 147456 + pix];
    float inv = 1.0f / (s + 2.2204460492503131e-16f);

    if (v == 0) {
#pragma unroll
        for (int c = 0; c < 32; c++)
            out_x1[c * 147456 + pix] = base[c * 147456 + pix] * inv;
    } else {
#pragma unroll
        for (int c = 0; c < 32; c++) {
            float val = base[c * 147456 + pix] * inv;
            base[c * 147456 + pix] = val;
            g_xp16[c * 147456 + pix] = __float2bfloat16(val);
        }
    }
}

// ===========================================================================
// Kernel 3: pack A (shifted/masked x1) to bf16; rows 736..767 zero.
// ===========================================================================
__global__ void __launch_bounds__(256) packA_kernel(const float* __restrict__ x1)
{
    const int CH = GEMM_K / 8;  // 17376
    int idx = blockIdx.x * 256 + threadIdx.x;
    if (idx >= 768 * CH) return;
    int r  = idx / CH;
    int c8 = idx % CH;
    int K0 = c8 * 8;
    int p  = K0 / 384;
    int q  = K0 % 384;

    __nv_bfloat16 v[8];
    if (r < 736) {
        int o = r / 23, w = r % 23;
        const float* src = x1 + o * 147456 + (11 + p) * 384 + 11 - w;
#pragma unroll
        for (int k = 0; k < 8; k++) {
            int qq = q + k;
            float f = (qq >= w && qq < 362 + w) ? src[qq] : 0.f;
            v[k] = __float2bfloat16(f);
        }
    } else {
#pragma unroll
        for (int k = 0; k < 8; k++) v[k] = __float2bfloat16(0.f);
    }
    uint4 pk;
    uint16_t* b = reinterpret_cast<uint16_t*>(&pk);
#pragma unroll
    for (int k = 0; k < 8; k++) b[k] = *reinterpret_cast<uint16_t*>(&v[k]);
    reinterpret_cast<uint4*>(g_A)[idx] = pk;
}

// ===========================================================================
// Kernel 4: mma.sync bf16 GEMM. grid (Nt:6, Mt:6, split:4), 512 threads.
// CTA tile 128x128, warp tile 32x32 (16 warps: 4 wm x 4 wn), kc=64,
// 4-stage cp.async, fragment pipeline carried across k-iterations.
// smem: 4 x A[128][72]bf16 + 4 x B[128][72]bf16 = 147456 B (stride 144 B).
// ===========================================================================
#define TILE_BYTES 18432            // 128*144
#define GEMM_SMEM  (8 * TILE_BYTES) // 147456

__global__ void __launch_bounds__(512, 1) gemm_kernel()
{
    extern __shared__ char smem[];
    const uint32_t sb = smem_u32(smem);
    const int tid = threadIdx.x;
    const int lane = tid & 31, wid = tid >> 5;
    const int Nt = blockIdx.x, Mt = blockIdx.y, sp = blockIdx.z;
    const int wm = wid & 3, wn = wid >> 2;   // warp tile: rows wm*32, cols wn*32
    const int g = lane >> 2, t4 = lane & 3;

    uint32_t bufA[4], bufB[4];
#pragma unroll
    for (int i = 0; i < 4; i++) {
        bufA[i] = sb + i * TILE_BYTES;
        bufB[i] = sb + (4 + i) * TILE_BYTES;
    }

    // ---- cp.async mapping: 512 threads, 2x16B chunks per operand per tile ----
    const int lr = tid >> 3;         // 0..63
    const int lc = tid & 7;          // 0..7
    const __nv_bfloat16* gA0 = g_A + (size_t)(Mt * 128 + lr) * GEMM_K + lc * 8;
    const __nv_bfloat16* gB0[2];
#pragma unroll
    for (int j = 0; j < 2; j++) {
        int n = Nt * 128 + lr + 64 * j;
        gB0[j] = g_xp16 + (size_t)(n / 23) * 147456 + (n % 23) * 384 + lc * 8;
    }
    const uint32_t dOff = (uint32_t)(lr * 144 + lc * 16);

    const int k0 = sp * IPS, k1 = k0 + IPS;

#define LOAD_TILE(kt, b) do {                                                  \
        size_t _ko = (size_t)(kt) * 64;                                        \
        _Pragma("unroll")                                                      \
        for (int _j = 0; _j < 2; _j++) {                                       \
            CP_ASYNC16(bufA[b] + dOff + _j * (64 * 144),                       \
                       gA0 + _ko + (size_t)_j * 64 * GEMM_K);                  \
            CP_ASYNC16(bufB[b] + dOff + _j * (64 * 144), gB0[_j] + _ko);       \
        }                                                                      \
    } while (0)

    LOAD_TILE(k0,     (k0) & 3);     CP_COMMIT();
    LOAD_TILE(k0 + 1, (k0 + 1) & 3); CP_COMMIT();
    LOAD_TILE(k0 + 2, (k0 + 2) & 3); CP_COMMIT();

    float acc[2][4][4];
#pragma unroll
    for (int mt = 0; mt < 2; mt++)
#pragma unroll
        for (int nt = 0; nt < 4; nt++)
#pragma unroll
            for (int e = 0; e < 4; e++) acc[mt][nt][e] = 0.f;

    // ---- per-lane ldmatrix offsets (bytes) ----
    const int matq = lane >> 3, rin = lane & 7;
    const uint32_t offA = (uint32_t)((((matq & 1) * 8 + rin) * 144) + (matq >> 1) * 16);
    const uint32_t offB = (uint32_t)((((matq >> 1) * 8 + rin) * 144) + (matq & 1) * 16);
    const uint32_t aRow = (uint32_t)(wm * 32) * 144;
    const uint32_t bRow = (uint32_t)(wn * 32) * 144;

    // fragment double buffers (pipeline carried across k-iterations)
    uint32_t Af[2][2][4], Bf[2][2][4];

#define LDS_ALL(fb, bA, bB, ks) do {                                           \
        _Pragma("unroll")                                                      \
        for (int _mt = 0; _mt < 2; _mt++)                                      \
            LDSM4(Af[fb][_mt][0], Af[fb][_mt][1], Af[fb][_mt][2], Af[fb][_mt][3], \
                  (bA) + aRow + _mt * (16 * 144) + (ks) * 32 + offA);          \
        _Pragma("unroll")                                                      \
        for (int _p = 0; _p < 2; _p++)                                         \
            LDSM4(Bf[fb][_p][0], Bf[fb][_p][1], Bf[fb][_p][2], Bf[fb][_p][3],  \
                  (bB) + bRow + _p * (16 * 144) + (ks) * 32 + offB);           \
    } while (0)

#define MMA_ALL(fb) do {                                                       \
        _Pragma("unroll")                                                      \
        for (int _p = 0; _p < 2; _p++) {                                       \
            _Pragma("unroll")                                                  \
            for (int _mt = 0; _mt < 2; _mt++) {                                \
                MMA16816(acc[_mt][2 * _p],     Af[fb][_mt][0], Af[fb][_mt][1], \
                         Af[fb][_mt][2], Af[fb][_mt][3], Bf[fb][_p][0], Bf[fb][_p][1]); \
                MMA16816(acc[_mt][2 * _p + 1], Af[fb][_mt][0], Af[fb][_mt][1], \
                         Af[fb][_mt][2], Af[fb][_mt][3], Bf[fb][_p][2], Bf[fb][_p][3]); \
            }                                                                  \
        }                                                                      \
    } while (0)

    // Prologue: tile k0 resident (3 committed, wait<=2), preload ks=0 frags.
    CP_WAIT2();
    __syncthreads();
    LDS_ALL(0, bufA[k0 & 3], bufB[k0 & 3], 0);

    for (int kt = k0; kt < k1; kt++) {
        CP_WAIT1();          // tiles kt and kt+1 resident
        __syncthreads();     // all warps done reading slot (kt+3)&3's old tile
        if (kt + 3 < k1) LOAD_TILE(kt + 3, (kt + 3) & 3);
        CP_COMMIT();         // unconditional (possibly empty group)

        const uint32_t cA = bufA[kt & 3],       cB = bufB[kt & 3];
        const uint32_t nA = bufA[(kt + 1) & 3], nB = bufB[(kt + 1) & 3];

        LDS_ALL(1, cA, cB, 1);  MMA_ALL(0);
        LDS_ALL(0, cA, cB, 2);  MMA_ALL(1);
        LDS_ALL(1, cA, cB, 3);  MMA_ALL(0);
        LDS_ALL(0, nA, nB, 0);  MMA_ALL(1);   // prefetch next tile's ks=0
    }

    // ---- epilogue: atomicAdd into g_acc (split-K reduction) ----
    const int row0 = Mt * 128 + wm * 32;
    const int col0 = Nt * 128 + wn * 32;
#pragma unroll
    for (int mt = 0; mt < 2; mt++) {
        int r_lo = row0 + mt * 16 + g;
        int r_hi = r_lo + 8;
#pragma unroll
        for (int nt = 0; nt < 4; nt++) {
            int c = col0 + nt * 8 + 2 * t4;
            bool c0ok = (c < 736), c1ok = (c + 1 < 736);
            if (r_lo < 736) {
                if (c0ok) atomicAdd(&g_acc[r_lo * 768 + c],     acc[mt][nt][0]);
                if (c1ok) atomicAdd(&g_acc[r_lo * 768 + c + 1], acc[mt][nt][1]);
            }
            if (r_hi < 736) {
                if (c0ok) atomicAdd(&g_acc[r_hi * 768 + c],     acc[mt][nt][2]);
                if (c1ok) atomicAdd(&g_acc[r_hi * 768 + c + 1], acc[mt][nt][3]);
            }
        }
    }
#undef LOAD_TILE
#undef LDS_ALL
#undef MMA_ALL
}

// ===========================================================================
// Kernel 5: assemble x2 from g_acc with permutation + scale
// ===========================================================================
__global__ void assemble_kernel(float* __restrict__ out_x2)
{
    int i = blockIdx.x * 256 + threadIdx.x;
    if (i >= 32 * 32 * 23 * 23) return;
    int w = i % 23;
    int t = i / 23;
    int h = t % 23; t /= 23;
    int d = t % 32;
    int o = t / 32;
    out_x2[i] = g_acc[(o * 23 + w) * 768 + (d * 23 + h)] * (1.0f / 131044.0f);
}

// ===========================================================================
// Launch
// ===========================================================================
extern "C" void kernel_launch(void* const* d_in, const int* in_sizes, int n_in,
                              void* d_out, int out_size)
{
    const float* x  = (const float*)d_in[0];
    const float* xp = (const float*)d_in[1];
    float* out = (float*)d_out;

    void *aft = nullptr, *afn = nullptr, *aacc = nullptr;
    cudaGetSymbolAddress(&aft, c_ft);
    cudaGetSymbolAddress(&afn, c_fn);
    cudaGetSymbolAddress(&aacc, g_acc);
    cudaMemcpyAsync(aft, d_in[2], 5808 * sizeof(float), cudaMemcpyDeviceToDevice, 0);
    cudaMemcpyAsync(afn, d_in[3], 1936 * sizeof(float), cudaMemcpyDeviceToDevice, 0);
    cudaMemsetAsync(aacc, 0, 768 * 768 * sizeof(float), 0);

    dim3 g1(6, 48, 2);
    feat_kernel<<<g1, 256>>>(x, xp);

    norm_kernel<<<(2 * 147456 + 255) / 256, 256>>>(out);

    packA_kernel<<<(768 * (GEMM_K / 8) + 255) / 256, 256>>>(out);

    static bool attr_set = false;
    if (!attr_set) {
        cudaFuncSetAttribute(gemm_kernel, cudaFuncAttributeMaxDynamicSharedMemorySize,
                             GEMM_SMEM);
        attr_set = true;
    }
    dim3 g4(6, 6, SPLITS);
    gemm_kernel<<<g4, 512, GEMM_SMEM>>>();

    assemble_kernel<<<(32 * 32 * 23 * 23 + 255) / 256, 256>>>(out + X1_ELEMS);
}